// round 11
// baseline (speedup 1.0000x reference)
#include <cuda_runtime.h>
#include <cuda_bf16.h>
#include <cstdint>

// Problem constants
#define BS     2
#define NM     10
#define NA     8400
#define NC     80
#define NPT    360
#define NBINS  36
#define NB2    72      // 5-degree buckets
#define NBM    (BS*NM)
#define BSNMNA (BS*NM*NA)
#define BSNA   (BS*NA)
#define MAXL   1024
#define FULLM  0xffffffffu
#define WPB    8       // warps per block in k_pairs
#define GX     128     // k_pairs grid.x
#define NBLK   (GX*NBM)
#define ABLK   66      // blocks in fused assign kernel (66*256 >= 16800)

// Output layout (flat float32, reference tuple order)
#define TL_OFF      0
#define TB_OFF      16800
#define TS_OFF      84000
#define MPB_OFF     1428000
#define TGI_OFF     1596000
#define GTDIST_OFF  1612800
#define CENT_OFF    7660800
#define FG_OFF      7828800
#define OUT_TOTAL   7845600
#define OUT_VEC4    (OUT_TOTAL/4)
#define ZPER        ((OUT_VEC4 + NBLK - 1)/NBLK)   // float4s per block slice

// Scratch. Written at live entries only; read at positive entries (pos ⊆ live).
// All control state returns to zero by replay end -> replay-invariant.
__device__ float g_align[BSNMNA];
__device__ float g_overlaps[BSNMNA];
__device__ float g_cent[BSNMNA];
__device__ __align__(16) float g_dist[(size_t)BSNMNA * NBINS];
__device__ int   g_liveA[NBM * MAXL];
__device__ int   g_cnt[NBM];
__device__ unsigned g_inbits[BSNA];
__device__ unsigned g_topkbits[BSNA];
__device__ unsigned g_posA[NBM];   // float bits of nonneg floats: uint order == float order
__device__ unsigned g_posO[NBM];
__device__ int g_blkdone[NBM];
__device__ unsigned g_bar1, g_bar2;

__device__ __forceinline__ unsigned long long ullmax2(unsigned long long a, unsigned long long b){ return a>b?a:b; }

// serial top-4 insertion on packed (ordkey<<32 | idx) keys (min-4)
__device__ __forceinline__ void ins4(unsigned long long key,
    unsigned long long& k0, unsigned long long& k1,
    unsigned long long& k2, unsigned long long& k3)
{
    if (key < k3) {
        k3 = key;
        unsigned long long tmp;
        if (k3 < k2) { tmp=k2; k2=k3; k3=tmp; }
        if (k2 < k1) { tmp=k1; k1=k2; k2=tmp; }
        if (k1 < k0) { tmp=k0; k0=k1; k1=tmp; }
    }
}

// ---------------------------------------------------------------------------
// K1: per-anchor in-box bitmask + compacted live lists (block-local counters)
// ---------------------------------------------------------------------------
__global__ __launch_bounds__(256) void k_compact(
    const float* __restrict__ anc,
    const float* __restrict__ gt_bboxes,
    const float* __restrict__ mask_gt)
{
    __shared__ float sbox[NBM][4];
    __shared__ float smgt[NBM];
    __shared__ int scnt_s[NBM], sbase[NBM];
    if (threadIdx.x < NBM) {
        sbox[threadIdx.x][0] = gt_bboxes[threadIdx.x*4+0];
        sbox[threadIdx.x][1] = gt_bboxes[threadIdx.x*4+1];
        sbox[threadIdx.x][2] = gt_bboxes[threadIdx.x*4+2];
        sbox[threadIdx.x][3] = gt_bboxes[threadIdx.x*4+3];
        smgt[threadIdx.x] = mask_gt[threadIdx.x];
        scnt_s[threadIdx.x] = 0;
    }
    __syncthreads();

    int t = blockIdx.x * blockDim.x + threadIdx.x;
    if (t < NBM) { g_posA[t] = 0u; g_posO[t] = 0u; }

    bool valid = t < BSNA;
    int b = valid ? (t / NA) : (BS - 1);
    int a = valid ? (t % NA) : 0;
    float2 p = valid ? ((const float2*)anc)[a] : make_float2(-1e9f, -1e9f);

    unsigned inb = 0;
    int posm[NM];
    #pragma unroll
    for (int m = 0; m < NM; m++) {
        int bm = b*NM + m;
        bool live = false;
        if (smgt[bm] != 0.f) {
            float mind = fminf(fminf(p.x - sbox[bm][0], p.y - sbox[bm][1]),
                               fminf(sbox[bm][2] - p.x, sbox[bm][3] - p.y));
            live = (mind > 1e-9f);
        }
        if (live) {
            inb |= (1u << m);
            posm[m] = atomicAdd(&scnt_s[bm], 1);   // independent counters: pipelined
        }
    }
    if (valid) g_inbits[t] = inb;
    __syncthreads();

    if (threadIdx.x < NBM && scnt_s[threadIdx.x] > 0)
        sbase[threadIdx.x] = atomicAdd(&g_cnt[threadIdx.x], scnt_s[threadIdx.x]);
    __syncthreads();

    #pragma unroll
    for (int m = 0; m < NM; m++) {
        if (inb & (1u << m)) {
            int bm = b*NM + m;
            int s = sbase[bm] + posm[m];
            if (s < MAXL) g_liveA[bm*MAXL + s] = a;
        }
    }
}

// ---------------------------------------------------------------------------
// K2: warp-per-pair (angle-free cos ordering) + zero-slice + fused top-13
// ---------------------------------------------------------------------------
struct WarpScratch {
    float2 uv[NPT];               // unit vectors, bucket-contiguous CSR order
    float r2[NPT];                // squared distance, indexed by point id
    unsigned short idxC[NPT];     // point ids, bucket-contiguous
    int scnt[NB2];
    int scur[NB2];
    int pfx2[3*NB2 + 1];          // tripled exclusive prefix (no mod in ring math)
    float dm[NBINS];
};

union SmemPool {
    WarpScratch ws[WPB];
    unsigned long long s_topk[MAXL];   // used only after block-wide syncthreads
};

__global__ __launch_bounds__(32*WPB) void k_pairs(
    const float* __restrict__ pd_scores,
    const float* __restrict__ pd_bboxes,
    const float* __restrict__ anc,
    const int*   __restrict__ gt_labels,
    const float* __restrict__ gt_coor,
    float4* __restrict__ out4)
{
    extern __shared__ unsigned char smem_raw[];
    SmemPool& sp = *reinterpret_cast<SmemPool*>(smem_raw);
    __shared__ int sLast;

    // zero-fill slice of the output (replaces memset node; overlaps compute)
    {
        int flat = blockIdx.y * gridDim.x + blockIdx.x;
        int base = flat * ZPER;
        int end = base + ZPER; if (end > OUT_VEC4) end = OUT_VEC4;
        float4 z = make_float4(0.f, 0.f, 0.f, 0.f);
        for (int i = base + threadIdx.x; i < end; i += 32*WPB) out4[i] = z;
    }

    int bm = blockIdx.y;
    int cnt = g_cnt[bm];
    if (cnt > MAXL) cnt = MAXL;
    if ((int)blockIdx.x * WPB >= cnt) return;   // no pair work for this block
    int nPart = (cnt + WPB - 1) / WPB;

    int wid = threadIdx.x >> 5;
    int lane = threadIdx.x & 31;
    int j = blockIdx.x * WPB + wid;
    int b = bm / NM;

    if (j < cnt) {
        WarpScratch& S = sp.ws[wid];
        const float2* gp2 = (const float2*)(gt_coor + (size_t)bm * (2*NPT));
        int label = gt_labels[bm];

        int a = g_liveA[bm*MAXL + j];
        float2 ap = ((const float2*)anc)[a];
        float ax = ap.x, ay = ap.y;
        int pairIdx = bm * NA + a;

        // zero 72 bucket counts
        S.scnt[lane] = 0;
        S.scnt[32 + lane] = 0;
        if (lane < 8) S.scnt[64 + lane] = 0;
        __syncwarp();

        // point phase: r2 + bucket via octant compares (no atan2)
        float2 dR[12];
        int    bkR[12];
        #pragma unroll
        for (int i = 0; i < 12; i++) {
            int p = lane + 32*i;
            if (p < NPT) {
                float2 pt = gp2[p];
                float dx = pt.x - ax, dy = pt.y - ay;
                S.r2[p] = dx*dx + dy*dy;
                dR[i] = make_float2(dx, dy);
                float axx = fabsf(dx), ayy = fabsf(dy);
                bool swp = ayy > axx;
                float mnv = swp ? axx : ayy, mxv = swp ? ayy : axx;
                float tt = __fdividef(mnv, mxv);
                int s = 0;
                s += (tt >= 0.087488665f);   // tan 5
                s += (tt >= 0.176326975f);   // tan 10
                s += (tt >= 0.267949194f);   // tan 15
                s += (tt >= 0.363970235f);   // tan 20
                s += (tt >= 0.466307656f);   // tan 25
                s += (tt >= 0.577350259f);   // tan 30
                s += (tt >= 0.700207531f);   // tan 35
                s += (tt >= 0.839099645f);   // tan 40
                s += (tt >= 1.0f);           // tan 45
                int rb = swp ? ((s == 9) ? 9 : 17 - s) : s;
                int bk;
                if (dx >= 0.f) bk = (dy >= 0.f) ? rb : 71 - rb;
                else           bk = (dy >= 0.f) ? 35 - rb : 36 + rb;
                if (bk < 0) bk = 0; if (bk > 71) bk = 71;
                bkR[i] = bk;
                atomicAdd(&S.scnt[bk], 1);
            }
        }
        __syncwarp();

        // exclusive scan over 72 counts -> tripled prefix pfx2 + cursors
        {
            int v0 = S.scnt[lane];
            int v1 = S.scnt[32 + lane];
            int v2 = (lane < 8) ? S.scnt[64 + lane] : 0;
            int c0 = v0, c1 = v1, c2 = v2;
            #pragma unroll
            for (int off = 1; off < 32; off <<= 1) {
                int n0 = __shfl_up_sync(FULLM, c0, off);
                int n1 = __shfl_up_sync(FULLM, c1, off);
                if (lane >= off) { c0 += n0; c1 += n1; }
            }
            int tot0 = __shfl_sync(FULLM, c0, 31);
            int tot01 = tot0 + __shfl_sync(FULLM, c1, 31);
            #pragma unroll
            for (int off = 1; off < 8; off <<= 1) {
                int n2 = __shfl_up_sync(FULLM, c2, off);
                if (lane >= off) c2 += n2;
            }
            int e0 = c0 - v0;
            int e1 = tot0 + c1 - v1;
            int e2 = tot01 + c2 - v2;
            S.scur[lane] = e0;
            S.pfx2[lane] = e0; S.pfx2[lane+NB2] = e0+NPT; S.pfx2[lane+2*NB2] = e0+2*NPT;
            int k1i = 32 + lane;
            S.scur[k1i] = e1;
            S.pfx2[k1i] = e1; S.pfx2[k1i+NB2] = e1+NPT; S.pfx2[k1i+2*NB2] = e1+2*NPT;
            if (lane < 8) {
                int k2i = 64 + lane;
                S.scur[k2i] = e2;
                S.pfx2[k2i] = e2; S.pfx2[k2i+NB2] = e2+NPT; S.pfx2[k2i+2*NB2] = e2+2*NPT;
            }
            if (lane == 0) S.pfx2[3*NB2] = 3*NPT;
        }
        __syncwarp();

        // scatter: unit vectors + ids, bucket-contiguous
        #pragma unroll
        for (int i = 0; i < 12; i++) {
            int p = lane + 32*i;
            if (p < NPT) {
                float dx = dR[i].x, dy = dR[i].y;
                float inv = rsqrtf(dx*dx + dy*dy);
                int pos = atomicAdd(&S.scur[bkR[i]], 1);
                S.uv[pos] = make_float2(dx*inv, dy*inv);
                S.idxC[pos] = (unsigned short)p;
            }
        }
        __syncwarp();

        // bin phase: one lane per bin; top-4 by largest cos(diff) (== smallest diff)
        for (int bb = lane; bb < NBINS; bb += 32) {
            int bin = bb;
            int i0 = 2*bin;
            float dmv;
            int c0cnt = S.pfx2[i0+73] - S.pfx2[i0+71];   // diff < 5 deg bucket pair
            if (c0cnt == 0) {
                dmv = 1e-6f;            // nearest candidate diff >= 5 > 3
            } else {
                int L = 0, lo, hi;
                for (;; L++) {
                    lo = S.pfx2[i0+71-L];
                    hi = S.pfx2[i0+73+L];
                    if (hi - lo >= 4) break;
                }
                int W, pos, n1;
                if (2*L + 2 >= NB2) { pos = 0; W = NPT; n1 = NPT; }
                else {
                    W = hi - lo;
                    pos = lo; while (pos >= NPT) pos -= NPT;
                    n1 = NPT - pos; if (n1 > W) n1 = W;
                }

                float cx, sx_;
                sincospif((float)bin / 18.0f, &sx_, &cx);   // bin*10 deg direction
                unsigned long long k0=~0ull,k1=~0ull,k2=~0ull,k3=~0ull;
                for (int c = 0; c < n1; c++) {
                    float2 u = S.uv[pos + c];
                    unsigned id = S.idxC[pos + c];
                    float cd = u.x*cx + u.y*sx_;
                    unsigned bf = __float_as_uint(cd);
                    unsigned ordv = (bf & 0x80000000u) ? ~bf : (bf | 0x80000000u);
                    ins4(((unsigned long long)(~ordv) << 32) | id, k0, k1, k2, k3);
                }
                for (int c = 0; c < W - n1; c++) {
                    float2 u = S.uv[c];
                    unsigned id = S.idxC[c];
                    float cd = u.x*cx + u.y*sx_;
                    unsigned bf = __float_as_uint(cd);
                    unsigned ordv = (bf & 0x80000000u) ? ~bf : (bf | 0x80000000u);
                    ins4(((unsigned long long)(~ordv) << 32) | id, k0, k1, k2, k3);
                }
                // decode best cos
                unsigned ordv0 = ~((unsigned)(k0 >> 32));
                float cos0 = (ordv0 & 0x80000000u) ? __uint_as_float(ordv0 ^ 0x80000000u)
                                                   : __uint_as_float(~ordv0);
                if (cos0 < 0.9986295347545738f) {   // cos 3 deg: min diff > 3
                    dmv = 1e-6f;
                } else {
                    float mr2 = S.r2[(unsigned)(k0 & 0xffffu)];
                    mr2 = fmaxf(mr2, S.r2[(unsigned)(k1 & 0xffffu)]);
                    mr2 = fmaxf(mr2, S.r2[(unsigned)(k2 & 0xffffu)]);
                    mr2 = fmaxf(mr2, S.r2[(unsigned)(k3 & 0xffffu)]);
                    dmv = fmaxf(sqrtf(mr2), 1e-6f);   // sqrt∘max == max∘sqrt
                }
            }
            S.dm[bin] = dmv;
        }
        __syncwarp();

        // coalesced g_dist write
        {
            float* gd = g_dist + (size_t)pairIdx * NBINS;
            gd[lane] = S.dm[lane];
            if (lane < 4) gd[32 + lane] = S.dm[32 + lane];
        }

        // epilogue: iou + centerness + align metric
        {
            float smin = 0.f, smax = 0.f, mn = 1e30f, mx = 0.f;
            const float* pb = pd_bboxes + ((size_t)b*NA + a) * NBINS;
            for (int e = lane; e < NBINS; e += 32) {
                float t = S.dm[e], p = pb[e];
                smin += fmaxf(fminf(t, p), 1e-6f);
                smax += fmaxf(t, p);
                mn = fminf(mn, t);
                mx = fmaxf(mx, t);
            }
            #pragma unroll
            for (int off = 16; off; off >>= 1) {
                smin += __shfl_xor_sync(FULLM, smin, off);
                smax += __shfl_xor_sync(FULLM, smax, off);
                mn = fminf(mn, __shfl_xor_sync(FULLM, mn, off));
                mx = fmaxf(mx, __shfl_xor_sync(FULLM, mx, off));
            }
            if (lane == 0) {
                float iou = smin / smax;
                float score = pd_scores[((size_t)b*NA + a) * NC + label];
                g_overlaps[pairIdx] = iou;
                g_align[pairIdx]    = score * iou * iou * iou;
                g_cent[pairIdx]     = sqrtf(mn / mx);
            }
        }
    }

    // ---- fused top-13: last finishing block of this bm runs the warp topk ----
    __syncthreads();            // also retires all ws usage before s_topk reuse
    if (threadIdx.x == 0) {
        __threadfence();                              // release g_align writes
        int old = atomicAdd(&g_blkdone[bm], 1);
        sLast = (old == nPart - 1) ? 1 : 0;
        if (sLast) g_blkdone[bm] = 0;                 // all arrived; reset for replay
    }
    __syncthreads();
    if (sLast && threadIdx.x < 32) {
        __threadfence();                              // acquire other blocks' writes
        const int* la = g_liveA + bm*MAXL;
        for (int jj = lane; jj < cnt; jj += 32) {
            int a = la[jj];
            float v = g_align[bm*NA + a];
            sp.s_topk[jj] = ((unsigned long long)__float_as_uint(v) << 32) | (unsigned)(NA - a);
        }
        __syncwarp();
        int m = bm % NM;
        int kmax = cnt < 13 ? cnt : 13;
        for (int k = 0; k < kmax; k++) {
            unsigned long long best = 0;
            for (int jj = lane; jj < cnt; jj += 32) best = ullmax2(best, sp.s_topk[jj]);
            #pragma unroll
            for (int off = 16; off; off >>= 1)
                best = ullmax2(best, __shfl_xor_sync(FULLM, best, off));
            if (best == 0) break;   // padding picks carry mask_pos=0 in reference
            for (int jj = lane; jj < cnt; jj += 32) if (sp.s_topk[jj] == best) sp.s_topk[jj] = 0;
            if (lane == 0) {
                int a = NA - (int)(best & 0xffffffffu);
                atomicOr(&g_topkbits[b*NA + a], 1u << m);
            }
            __syncwarp();
        }
    }
}

// ---------------------------------------------------------------------------
// K3: fused per-anchor resolution + outputs + grid barrier + target_scores
// ---------------------------------------------------------------------------
__global__ __launch_bounds__(256) void k_assign(
    const int*   __restrict__ gt_labels,
    const float* __restrict__ gt_bboxes,
    float* __restrict__ out)
{
    int t = blockIdx.x * blockDim.x + threadIdx.x;
    bool valid = t < BSNA;
    unsigned fin = 0;
    int b = 0, a = 0;

    if (valid) {
        b = t / NA; a = t % NA;
        unsigned tb  = g_topkbits[t];
        unsigned inb = g_inbits[t];
        g_topkbits[t] = 0u;               // reset for next replay
        fin = tb;
        if (__popc(tb) > 1) {
            float best = -1.f; int bi = 0;
            #pragma unroll
            for (int m = 0; m < NM; m++) {
                float o = ((inb >> m) & 1u) ? g_overlaps[(b*NM+m)*NA + a] : 0.f;
                if (o > best) { best = o; bi = m; }   // first max kept
            }
            fin = 1u << bi;
        }

        int tgt = fin ? (__ffs(fin) - 1) : 0;
        out[FG_OFF + t]  = fin ? 1.f : 0.f;
        out[TGI_OFF + t] = (float)tgt;
        int lbl = gt_labels[b*NM + tgt]; if (lbl < 0) lbl = 0;
        out[TL_OFF + t] = (float)lbl;
        const float4* gb4 = (const float4*)(gt_bboxes);
        ((float4*)(out + TB_OFF))[t] = gb4[b*NM + tgt];

        if (fin) {
            int idx = (b*NM + tgt)*NA + a;
            out[MPB_OFF + idx]  = 1.f;
            out[CENT_OFF + idx] = g_cent[idx];
            atomicMax(&g_posA[b*NM + tgt], __float_as_uint(g_align[idx]));
            atomicMax(&g_posO[b*NM + tgt], __float_as_uint(g_overlaps[idx]));
            const float4* src = (const float4*)(g_dist + (size_t)idx * NBINS);
            float4* dst = (float4*)(out + GTDIST_OFF + (size_t)idx * NBINS);
            #pragma unroll
            for (int e = 0; e < NBINS/4; e++) dst[e] = src[e];
        }
    }
    if (t < NBM) g_cnt[t] = 0;            // reset for next replay (k_pairs done)

    // ---- software grid barrier (two counters; all ABLK blocks co-resident) ----
    if (threadIdx.x == 0) {
        __threadfence();
        atomicAdd(&g_bar1, 1u);
        while (*((volatile unsigned*)&g_bar1) < ABLK) { }
        __threadfence();
        unsigned o2 = atomicAdd(&g_bar2, 1u);
        if (o2 == ABLK - 1) {             // everyone passed the spin
            atomicExch(&g_bar1, 0u);
            atomicExch(&g_bar2, 0u);
        }
    }
    __syncthreads();

    // ---- phase 2: target_scores for positives ----
    if (valid && fin) {
        int m = __ffs(fin) - 1;
        int bm = b*NM + m;
        float A = __uint_as_float(g_posA[bm]);
        float O = __uint_as_float(g_posO[bm]);
        float norm = g_align[bm*NA + a] * O / (A + 1e-9f);
        int lbl = gt_labels[bm]; if (lbl < 0) lbl = 0;
        out[TS_OFF + (size_t)t * NC + lbl] = norm;
    }
}

// ---------------------------------------------------------------------------
extern "C" void kernel_launch(void* const* d_in, const int* in_sizes, int n_in,
                              void* d_out, int out_size) {
    const float* pd_scores = (const float*)d_in[0];
    const float* pd_bboxes = (const float*)d_in[1];
    const float* anc       = (const float*)d_in[2];
    const int*   gt_labels = (const int*)  d_in[3];
    const float* gt_bboxes = (const float*)d_in[4];
    const float* mask_gt   = (const float*)d_in[5];
    const float* gt_coor   = (const float*)d_in[6];
    float* out = (float*)d_out;

    cudaFuncSetAttribute(k_pairs, cudaFuncAttributeMaxDynamicSharedMemorySize,
                         (int)sizeof(SmemPool));
    k_compact<<<(BSNA + 255)/256, 256>>>(anc, gt_bboxes, mask_gt);
    dim3 g1(GX, NBM);
    k_pairs<<<g1, 32*WPB, sizeof(SmemPool)>>>(pd_scores, pd_bboxes, anc, gt_labels,
                                              gt_coor, (float4*)out);
    k_assign<<<ABLK, 256>>>(gt_labels, gt_bboxes, out);
}

// round 12
// speedup vs baseline: 1.2922x; 1.2922x over previous
#include <cuda_runtime.h>
#include <cuda_bf16.h>
#include <cstdint>

// Problem constants
#define BS     2
#define NM     10
#define NA     8400
#define NC     80
#define NPT    360
#define NBINS  36
#define NB2    72      // 5-degree buckets
#define NBM    (BS*NM)
#define BSNMNA (BS*NM*NA)
#define BSNA   (BS*NA)
#define MAXL   1024
#define FULLM  0xffffffffu
#define WPB    8       // warps per block in k_pairs
#define ABLK   66      // blocks in fused assign kernel (66*256 >= 16800)

// Output layout (flat float32, reference tuple order)
#define TL_OFF      0
#define TB_OFF      16800
#define TS_OFF      84000
#define MPB_OFF     1428000
#define TGI_OFF     1596000
#define GTDIST_OFF  1612800
#define CENT_OFF    7660800
#define FG_OFF      7828800
#define OUT_TOTAL   7845600

// Scratch. Written at live entries only; read at positive entries (pos ⊆ live).
// All control state returns to zero by replay end -> replay-invariant.
__device__ float g_align[BSNMNA];
__device__ float g_overlaps[BSNMNA];
__device__ float g_cent[BSNMNA];
__device__ __align__(16) float g_dist[(size_t)BSNMNA * NBINS];
__device__ int   g_liveA[NBM * MAXL];
__device__ int   g_cnt[NBM];
__device__ unsigned g_inbits[BSNA];
__device__ unsigned g_topkbits[BSNA];
__device__ unsigned g_posA[NBM];   // float bits of nonneg floats: uint order == float order
__device__ unsigned g_posO[NBM];
__device__ int g_blkdone[NBM];
__device__ unsigned g_bar1, g_bar2;

__device__ __forceinline__ unsigned long long ullmax2(unsigned long long a, unsigned long long b){ return a>b?a:b; }

// serial top-4 insertion on packed (ordkey<<32 | idx) keys (min-4)
__device__ __forceinline__ void ins4(unsigned long long key,
    unsigned long long& k0, unsigned long long& k1,
    unsigned long long& k2, unsigned long long& k3)
{
    if (key < k3) {
        k3 = key;
        unsigned long long tmp;
        if (k3 < k2) { tmp=k2; k2=k3; k3=tmp; }
        if (k2 < k1) { tmp=k1; k1=k2; k2=tmp; }
        if (k1 < k0) { tmp=k0; k0=k1; k1=tmp; }
    }
}

// ---------------------------------------------------------------------------
// K1: per-anchor in-box bitmask + compacted live lists (warp-aggregated; R10)
// ---------------------------------------------------------------------------
__global__ __launch_bounds__(256) void k_compact(
    const float* __restrict__ anc,
    const float* __restrict__ gt_bboxes,
    const float* __restrict__ mask_gt)
{
    __shared__ float sbox[NBM][4];
    __shared__ float smgt[NBM];
    if (threadIdx.x < NBM) {
        sbox[threadIdx.x][0] = gt_bboxes[threadIdx.x*4+0];
        sbox[threadIdx.x][1] = gt_bboxes[threadIdx.x*4+1];
        sbox[threadIdx.x][2] = gt_bboxes[threadIdx.x*4+2];
        sbox[threadIdx.x][3] = gt_bboxes[threadIdx.x*4+3];
        smgt[threadIdx.x] = mask_gt[threadIdx.x];
    }
    __syncthreads();

    int t = blockIdx.x * blockDim.x + threadIdx.x;
    if (t < NBM) { g_posA[t] = 0u; g_posO[t] = 0u; }

    bool valid = t < BSNA;
    int b = valid ? (t / NA) : (BS - 1);
    int a = valid ? (t % NA) : 0;
    float2 p = valid ? ((const float2*)anc)[a] : make_float2(-1e9f, -1e9f);
    int lane = threadIdx.x & 31;
    unsigned grp = __match_any_sync(FULLM, b);   // lanes sharing batch index

    unsigned inb = 0;
    #pragma unroll
    for (int m = 0; m < NM; m++) {
        int bm = b*NM + m;
        bool live = false;
        if (smgt[bm] != 0.f) {
            float mind = fminf(fminf(p.x - sbox[bm][0], p.y - sbox[bm][1]),
                               fminf(sbox[bm][2] - p.x, sbox[bm][3] - p.y));
            live = (mind > 1e-9f);
        }
        unsigned set = __ballot_sync(FULLM, live) & grp;
        int leader = __ffs(set) - 1;
        int base = 0;
        if (live && lane == leader) base = atomicAdd(&g_cnt[bm], __popc(set));
        base = __shfl_sync(FULLM, base, leader >= 0 ? leader : 0);
        if (live) {
            inb |= (1u << m);
            int s = base + __popc(set & ((1u << lane) - 1u));
            if (s < MAXL) g_liveA[bm*MAXL + s] = a;
        }
    }
    if (valid) g_inbits[t] = inb;
}

// ---------------------------------------------------------------------------
// K2: warp-per-pair (angle-free cos ordering, compact smem) + fused top-13
// ---------------------------------------------------------------------------
struct WarpScratch {
    float2 uv[NPT];               // unit vectors, bucket-contiguous CSR order  2880B
    float r2[NPT];                // squared distance, by point id              1440B
    unsigned short idxC[NPT];     // point ids, bucket-contiguous                720B
    int scur[NB2];                // scatter cursors                             288B
    int pfxW[108];                // prefix window [g-54], g in [54,161]         432B
                                  // (scnt aliased into pfxW[0..71] pre-scan)
};                                // total 5760B

union SmemPool {
    WarpScratch ws[WPB];               // 46080B
    unsigned long long s_topk[MAXL];   // used only after block-wide syncthreads
};

__global__ __launch_bounds__(32*WPB) void k_pairs(
    const float* __restrict__ pd_scores,
    const float* __restrict__ pd_bboxes,
    const float* __restrict__ anc,
    const int*   __restrict__ gt_labels,
    const float* __restrict__ gt_coor)
{
    __shared__ SmemPool sp;
    __shared__ int sLast;

    int bm = blockIdx.y;
    int cnt = g_cnt[bm];
    if (cnt > MAXL) cnt = MAXL;
    if ((int)blockIdx.x * WPB >= cnt) return;   // whole block idle
    int nPart = (cnt + WPB - 1) / WPB;

    int wid = threadIdx.x >> 5;
    int lane = threadIdx.x & 31;
    int j = blockIdx.x * WPB + wid;
    int b = bm / NM;

    if (j < cnt) {
        WarpScratch& S = sp.ws[wid];
        int* scnt = S.pfxW;               // alias: counts live before prefix write
        const float2* gp2 = (const float2*)(gt_coor + (size_t)bm * (2*NPT));
        int label = gt_labels[bm];

        int a = g_liveA[bm*MAXL + j];
        float2 ap = ((const float2*)anc)[a];
        float ax = ap.x, ay = ap.y;
        int pairIdx = bm * NA + a;

        // zero 72 bucket counts
        scnt[lane] = 0;
        scnt[32 + lane] = 0;
        if (lane < 8) scnt[64 + lane] = 0;
        __syncwarp();

        // point phase: r2 + bucket via octant compares (no atan2)
        float2 dR[12];
        int    bkR[12];
        #pragma unroll
        for (int i = 0; i < 12; i++) {
            int p = lane + 32*i;
            if (p < NPT) {
                float2 pt = gp2[p];
                float dx = pt.x - ax, dy = pt.y - ay;
                S.r2[p] = dx*dx + dy*dy;
                dR[i] = make_float2(dx, dy);
                float axx = fabsf(dx), ayy = fabsf(dy);
                bool swp = ayy > axx;
                float mnv = swp ? axx : ayy, mxv = swp ? ayy : axx;
                float tt = __fdividef(mnv, mxv);
                int s = 0;
                s += (tt >= 0.087488665f);   // tan 5
                s += (tt >= 0.176326975f);   // tan 10
                s += (tt >= 0.267949194f);   // tan 15
                s += (tt >= 0.363970235f);   // tan 20
                s += (tt >= 0.466307656f);   // tan 25
                s += (tt >= 0.577350259f);   // tan 30
                s += (tt >= 0.700207531f);   // tan 35
                s += (tt >= 0.839099645f);   // tan 40
                s += (tt >= 1.0f);           // tan 45
                int rb = swp ? ((s == 9) ? 9 : 17 - s) : s;
                int bk;
                if (dx >= 0.f) bk = (dy >= 0.f) ? rb : 71 - rb;
                else           bk = (dy >= 0.f) ? 35 - rb : 36 + rb;
                if (bk < 0) bk = 0; if (bk > 71) bk = 71;
                bkR[i] = bk;
                atomicAdd(&scnt[bk], 1);
            }
        }
        __syncwarp();

        // exclusive scan over 72 counts (read fully into regs, then overwrite pfxW)
        {
            int v0 = scnt[lane];
            int v1 = scnt[32 + lane];
            int v2 = (lane < 8) ? scnt[64 + lane] : 0;
            __syncwarp();                 // all reads done before pfxW writes
            int c0 = v0, c1 = v1, c2 = v2;
            #pragma unroll
            for (int off = 1; off < 32; off <<= 1) {
                int n0 = __shfl_up_sync(FULLM, c0, off);
                int n1 = __shfl_up_sync(FULLM, c1, off);
                if (lane >= off) { c0 += n0; c1 += n1; }
            }
            int tot0 = __shfl_sync(FULLM, c0, 31);
            int tot01 = tot0 + __shfl_sync(FULLM, c1, 31);
            #pragma unroll
            for (int off = 1; off < 8; off <<= 1) {
                int n2 = __shfl_up_sync(FULLM, c2, off);
                if (lane >= off) c2 += n2;
            }
            int e0 = c0 - v0;
            int e1 = tot0 + c1 - v1;
            int e2 = tot01 + c2 - v2;
            // k = lane (copy c: g=k+72c, local=g-54)
            S.scur[lane] = e0;
            S.pfxW[lane + 18] = e0 + NPT;                   // c1
            if (lane <= 17) S.pfxW[lane + 90] = e0 + 2*NPT; // c2
            int k1i = 32 + lane;                            // k in [32,63]
            S.scur[k1i] = e1;
            S.pfxW[k1i + 18] = e1 + NPT;                    // c1
            if (lane < 8) {
                int k2i = 64 + lane;                        // k in [64,71]
                S.scur[k2i] = e2;
                S.pfxW[k2i - 54] = e2;                      // c0 (k>=54)
                S.pfxW[k2i + 18] = e2 + NPT;                // c1
            }
            // c0 for k in [54,63]: lanes 22..31 hold e1 of k=32+lane
            if (lane >= 22) S.pfxW[k1i - 54] = e1;
        }
        __syncwarp();

        // scatter: unit vectors + ids, bucket-contiguous
        #pragma unroll
        for (int i = 0; i < 12; i++) {
            int p = lane + 32*i;
            if (p < NPT) {
                float dx = dR[i].x, dy = dR[i].y;
                float inv = rsqrtf(dx*dx + dy*dy);
                int pos = atomicAdd(&S.scur[bkR[i]], 1);
                S.uv[pos] = make_float2(dx*inv, dy*inv);
                S.idxC[pos] = (unsigned short)p;
            }
        }
        __syncwarp();

        // bin phase: one lane per bin; top-4 by largest cos(diff) (== smallest diff)
        float dmv0 = 0.f, dmv1 = 0.f;
        #pragma unroll
        for (int pass = 0; pass < 2; pass++) {
            int bin = lane + 32*pass;
            if (pass == 1 && lane >= 4) break;
            int i0 = 2*bin;
            float dmv;
            int c0cnt = S.pfxW[i0+19] - S.pfxW[i0+17];   // diff < 5 deg bucket pair
            if (c0cnt == 0) {
                dmv = 1e-6f;            // nearest candidate diff >= 5 > 3
            } else {
                int L = 0, lo = 0, hi = 0; bool full = false;
                for (;; L++) {
                    if (L >= 17) { full = true; break; }   // window > 180deg: full scan
                    lo = S.pfxW[i0+17-L];
                    hi = S.pfxW[i0+19+L];
                    if (hi - lo >= 4) break;
                }
                int W, pos, n1;
                if (full) { pos = 0; W = NPT; n1 = NPT; }
                else {
                    W = hi - lo;
                    pos = lo; while (pos >= NPT) pos -= NPT;
                    n1 = NPT - pos; if (n1 > W) n1 = W;
                }

                float cx, sx_;
                sincospif((float)bin / 18.0f, &sx_, &cx);   // bin*10 deg direction
                unsigned long long k0=~0ull,k1=~0ull,k2=~0ull,k3=~0ull;
                for (int c = 0; c < n1; c++) {
                    float2 u = S.uv[pos + c];
                    unsigned id = S.idxC[pos + c];
                    float cd = u.x*cx + u.y*sx_;
                    unsigned bf = __float_as_uint(cd);
                    unsigned ordv = (bf & 0x80000000u) ? ~bf : (bf | 0x80000000u);
                    ins4(((unsigned long long)(~ordv) << 32) | id, k0, k1, k2, k3);
                }
                for (int c = 0; c < W - n1; c++) {
                    float2 u = S.uv[c];
                    unsigned id = S.idxC[c];
                    float cd = u.x*cx + u.y*sx_;
                    unsigned bf = __float_as_uint(cd);
                    unsigned ordv = (bf & 0x80000000u) ? ~bf : (bf | 0x80000000u);
                    ins4(((unsigned long long)(~ordv) << 32) | id, k0, k1, k2, k3);
                }
                unsigned ordv0 = ~((unsigned)(k0 >> 32));
                float cos0 = (ordv0 & 0x80000000u) ? __uint_as_float(ordv0 ^ 0x80000000u)
                                                   : __uint_as_float(~ordv0);
                if (cos0 < 0.9986295347545738f) {   // cos 3 deg: min diff > 3
                    dmv = 1e-6f;
                } else {
                    float mr2 = S.r2[(unsigned)(k0 & 0xffffu)];
                    mr2 = fmaxf(mr2, S.r2[(unsigned)(k1 & 0xffffu)]);
                    mr2 = fmaxf(mr2, S.r2[(unsigned)(k2 & 0xffffu)]);
                    mr2 = fmaxf(mr2, S.r2[(unsigned)(k3 & 0xffffu)]);
                    dmv = fmaxf(sqrtf(mr2), 1e-6f);   // sqrt∘max == max∘sqrt
                }
            }
            if (pass == 0) dmv0 = dmv; else dmv1 = dmv;
        }
        __syncwarp();

        // coalesced g_dist write (each lane owns its bins)
        {
            float* gd = g_dist + (size_t)pairIdx * NBINS;
            gd[lane] = dmv0;
            if (lane < 4) gd[32 + lane] = dmv1;
        }

        // epilogue: iou + centerness + align metric (lane-owned dm values)
        {
            const float* pb = pd_bboxes + ((size_t)b*NA + a) * NBINS;
            float p0 = pb[lane];
            float smin = fmaxf(fminf(dmv0, p0), 1e-6f);
            float smax = fmaxf(dmv0, p0);
            float mn = dmv0, mx = dmv0;
            if (lane < 4) {
                float p1 = pb[32 + lane];
                smin += fmaxf(fminf(dmv1, p1), 1e-6f);
                smax += fmaxf(dmv1, p1);
                mn = fminf(mn, dmv1);
                mx = fmaxf(mx, dmv1);
            }
            #pragma unroll
            for (int off = 16; off; off >>= 1) {
                smin += __shfl_xor_sync(FULLM, smin, off);
                smax += __shfl_xor_sync(FULLM, smax, off);
                mn = fminf(mn, __shfl_xor_sync(FULLM, mn, off));
                mx = fmaxf(mx, __shfl_xor_sync(FULLM, mx, off));
            }
            if (lane == 0) {
                float iou = smin / smax;
                float score = pd_scores[((size_t)b*NA + a) * NC + label];
                g_overlaps[pairIdx] = iou;
                g_align[pairIdx]    = score * iou * iou * iou;
                g_cent[pairIdx]     = sqrtf(mn / mx);
            }
        }
    }

    // ---- fused top-13: last finishing block of this bm runs the warp topk ----
    __syncthreads();            // also retires all ws usage before s_topk reuse
    if (threadIdx.x == 0) {
        __threadfence();                              // release g_align writes
        int old = atomicAdd(&g_blkdone[bm], 1);
        sLast = (old == nPart - 1) ? 1 : 0;
        if (sLast) g_blkdone[bm] = 0;                 // all arrived; reset for replay
    }
    __syncthreads();
    if (sLast && threadIdx.x < 32) {
        __threadfence();                              // acquire other blocks' writes
        const int* la = g_liveA + bm*MAXL;
        for (int jj = lane; jj < cnt; jj += 32) {
            int a = la[jj];
            float v = g_align[bm*NA + a];
            sp.s_topk[jj] = ((unsigned long long)__float_as_uint(v) << 32) | (unsigned)(NA - a);
        }
        __syncwarp();
        int m = bm % NM;
        int kmax = cnt < 13 ? cnt : 13;
        for (int k = 0; k < kmax; k++) {
            unsigned long long best = 0;
            for (int jj = lane; jj < cnt; jj += 32) best = ullmax2(best, sp.s_topk[jj]);
            #pragma unroll
            for (int off = 16; off; off >>= 1)
                best = ullmax2(best, __shfl_xor_sync(FULLM, best, off));
            if (best == 0) break;   // padding picks carry mask_pos=0 in reference
            for (int jj = lane; jj < cnt; jj += 32) if (sp.s_topk[jj] == best) sp.s_topk[jj] = 0;
            if (lane == 0) {
                int a = NA - (int)(best & 0xffffffffu);
                atomicOr(&g_topkbits[b*NA + a], 1u << m);
            }
            __syncwarp();
        }
    }
}

// ---------------------------------------------------------------------------
// K3: fused per-anchor resolution + outputs + grid barrier + target_scores
// ---------------------------------------------------------------------------
__global__ __launch_bounds__(256) void k_assign(
    const int*   __restrict__ gt_labels,
    const float* __restrict__ gt_bboxes,
    float* __restrict__ out)
{
    int t = blockIdx.x * blockDim.x + threadIdx.x;
    bool valid = t < BSNA;
    unsigned fin = 0;
    int b = 0, a = 0;

    if (valid) {
        b = t / NA; a = t % NA;
        unsigned tb  = g_topkbits[t];
        unsigned inb = g_inbits[t];
        g_topkbits[t] = 0u;               // reset for next replay
        fin = tb;
        if (__popc(tb) > 1) {
            float best = -1.f; int bi = 0;
            #pragma unroll
            for (int m = 0; m < NM; m++) {
                float o = ((inb >> m) & 1u) ? g_overlaps[(b*NM+m)*NA + a] : 0.f;
                if (o > best) { best = o; bi = m; }   // first max kept
            }
            fin = 1u << bi;
        }

        int tgt = fin ? (__ffs(fin) - 1) : 0;
        out[FG_OFF + t]  = fin ? 1.f : 0.f;
        out[TGI_OFF + t] = (float)tgt;
        int lbl = gt_labels[b*NM + tgt]; if (lbl < 0) lbl = 0;
        out[TL_OFF + t] = (float)lbl;
        const float4* gb4 = (const float4*)(gt_bboxes);
        ((float4*)(out + TB_OFF))[t] = gb4[b*NM + tgt];

        if (fin) {
            int idx = (b*NM + tgt)*NA + a;
            out[MPB_OFF + idx]  = 1.f;
            out[CENT_OFF + idx] = g_cent[idx];
            atomicMax(&g_posA[b*NM + tgt], __float_as_uint(g_align[idx]));
            atomicMax(&g_posO[b*NM + tgt], __float_as_uint(g_overlaps[idx]));
            const float4* src = (const float4*)(g_dist + (size_t)idx * NBINS);
            float4* dst = (float4*)(out + GTDIST_OFF + (size_t)idx * NBINS);
            #pragma unroll
            for (int e = 0; e < NBINS/4; e++) dst[e] = src[e];
        }
    }
    if (t < NBM) g_cnt[t] = 0;            // reset for next replay (k_pairs done)

    // ---- software grid barrier (two counters; all ABLK blocks co-resident) ----
    if (threadIdx.x == 0) {
        __threadfence();
        atomicAdd(&g_bar1, 1u);
        while (*((volatile unsigned*)&g_bar1) < ABLK) { }
        __threadfence();
        unsigned o2 = atomicAdd(&g_bar2, 1u);
        if (o2 == ABLK - 1) {             // everyone passed the spin
            atomicExch(&g_bar1, 0u);
            atomicExch(&g_bar2, 0u);
        }
    }
    __syncthreads();

    // ---- phase 2: target_scores for positives ----
    if (valid && fin) {
        int m = __ffs(fin) - 1;
        int bm = b*NM + m;
        float A = __uint_as_float(g_posA[bm]);
        float O = __uint_as_float(g_posO[bm]);
        float norm = g_align[bm*NA + a] * O / (A + 1e-9f);
        int lbl = gt_labels[bm]; if (lbl < 0) lbl = 0;
        out[TS_OFF + (size_t)t * NC + lbl] = norm;
    }
}

// ---------------------------------------------------------------------------
extern "C" void kernel_launch(void* const* d_in, const int* in_sizes, int n_in,
                              void* d_out, int out_size) {
    const float* pd_scores = (const float*)d_in[0];
    const float* pd_bboxes = (const float*)d_in[1];
    const float* anc       = (const float*)d_in[2];
    const int*   gt_labels = (const int*)  d_in[3];
    const float* gt_bboxes = (const float*)d_in[4];
    const float* mask_gt   = (const float*)d_in[5];
    const float* gt_coor   = (const float*)d_in[6];
    float* out = (float*)d_out;

    cudaMemsetAsync(out, 0, (size_t)OUT_TOTAL * sizeof(float));
    k_compact<<<(BSNA + 255)/256, 256>>>(anc, gt_bboxes, mask_gt);
    dim3 g1((MAXL + WPB - 1)/WPB, NBM);
    k_pairs<<<g1, 32*WPB>>>(pd_scores, pd_bboxes, anc, gt_labels, gt_coor);
    k_assign<<<ABLK, 256>>>(gt_labels, gt_bboxes, out);
}

// round 13
// speedup vs baseline: 1.4346x; 1.1102x over previous
#include <cuda_runtime.h>
#include <cuda_bf16.h>
#include <cstdint>

// Problem constants
#define BS     2
#define NM     10
#define NA     8400
#define NAP    8416    // padded per-bm span (263*32): warps never straddle a bm
#define NC     80
#define NPT    360
#define NBINS  36
#define NB2    72      // 5-degree buckets
#define NBM    (BS*NM)
#define BSNMNA (BS*NM*NA)
#define BSNA   (BS*NA)
#define MAXL   1024
#define FULLM  0xffffffffu
#define WPB    8       // warps per block in k_pairs
#define ABLK   66      // blocks in fused assign kernel (66*256 >= 16800)

// Output layout (flat float32, reference tuple order)
#define TL_OFF      0
#define TB_OFF      16800
#define TS_OFF      84000
#define MPB_OFF     1428000
#define TGI_OFF     1596000
#define GTDIST_OFF  1612800
#define CENT_OFF    7660800
#define FG_OFF      7828800
#define OUT_TOTAL   7845600

// Scratch. Written at live entries only; read at positive entries (pos ⊆ live).
// All control state returns to zero by replay end -> replay-invariant.
__device__ float g_align[BSNMNA];
__device__ float g_overlaps[BSNMNA];
__device__ float g_cent[BSNMNA];
__device__ __align__(16) float g_dist[(size_t)BSNMNA * NBINS];
__device__ int   g_liveA[NBM * MAXL];
__device__ int   g_cnt[NBM];
__device__ unsigned g_inbits[BSNA];     // sparse atomicOr; re-zeroed by k_assign
__device__ unsigned g_topkbits[BSNA];
__device__ unsigned g_posA[NBM];   // float bits of nonneg floats: uint order == float order
__device__ unsigned g_posO[NBM];
__device__ int g_blkdone[NBM];
__device__ unsigned g_bar1, g_bar2;

__device__ __forceinline__ unsigned long long ullmax2(unsigned long long a, unsigned long long b){ return a>b?a:b; }

// serial top-4 insertion on packed (df_bits<<32 | idx) keys
__device__ __forceinline__ void ins4(unsigned long long key,
    unsigned long long& k0, unsigned long long& k1,
    unsigned long long& k2, unsigned long long& k3)
{
    if (key < k3) {
        k3 = key;
        unsigned long long tmp;
        if (k3 < k2) { tmp=k2; k2=k3; k3=tmp; }
        if (k2 < k1) { tmp=k1; k1=k2; k2=tmp; }
        if (k1 < k0) { tmp=k0; k0=k1; k1=tmp; }
    }
}

// ---------------------------------------------------------------------------
// K1: one thread per (bm, anchor); single ballot round; sparse inbits
// ---------------------------------------------------------------------------
__global__ __launch_bounds__(256) void k_compact(
    const float* __restrict__ anc,
    const float* __restrict__ gt_bboxes,
    const float* __restrict__ mask_gt)
{
    int t = blockIdx.x * blockDim.x + threadIdx.x;
    if (t < NBM) { g_posA[t] = 0u; g_posO[t] = 0u; }
    if (t >= NBM * NAP) return;

    int bm = t / NAP;
    int a  = t - bm * NAP;
    int lane = threadIdx.x & 31;

    bool live = false;
    if (a < NA && __ldg(&mask_gt[bm]) != 0.f) {
        float2 p = __ldg(&((const float2*)anc)[a]);
        float lx = __ldg(&gt_bboxes[bm*4+0]);
        float ly = __ldg(&gt_bboxes[bm*4+1]);
        float rx = __ldg(&gt_bboxes[bm*4+2]);
        float ry = __ldg(&gt_bboxes[bm*4+3]);
        float mind = fminf(fminf(p.x - lx, p.y - ly), fminf(rx - p.x, ry - p.y));
        live = (mind > 1e-9f);
    }
    unsigned set = __ballot_sync(FULLM, live);   // whole warp shares one bm
    if (set) {
        int leader = __ffs(set) - 1;
        int base = 0;
        if (lane == leader) base = atomicAdd(&g_cnt[bm], __popc(set));
        base = __shfl_sync(FULLM, base, leader);
        if (live) {
            int s = base + __popc(set & ((1u << lane) - 1u));
            if (s < MAXL) g_liveA[bm*MAXL + s] = a;
            int b = bm / NM, m = bm - b*NM;
            atomicOr(&g_inbits[b*NA + a], 1u << m);
        }
    }
}

// ---------------------------------------------------------------------------
// K2: warp-per-pair heavy work (R10 version: atan2 + 5-deg buckets) + top-13
// ---------------------------------------------------------------------------
struct WarpScratch {
    unsigned long long sAI[NPT];  // (ang_bits<<32)|idx, bucket-contiguous CSR
    float r2[NPT];                // squared distance, indexed by point id
    int scnt[NB2];
    int scur[NB2];
    int pfx2[3*NB2 + 1];          // tripled exclusive prefix (no mod in ring math)
    float dm[NBINS];
};

union SmemPool {
    WarpScratch ws[WPB];
    unsigned long long s_topk[MAXL];   // used only after block-wide syncthreads
};

__global__ __launch_bounds__(32*WPB) void k_pairs(
    const float* __restrict__ pd_scores,
    const float* __restrict__ pd_bboxes,
    const float* __restrict__ anc,
    const int*   __restrict__ gt_labels,
    const float* __restrict__ gt_coor)
{
    __shared__ SmemPool sp;
    __shared__ int sLast;

    int bm = blockIdx.y;
    int cnt = g_cnt[bm];
    if (cnt > MAXL) cnt = MAXL;
    if ((int)blockIdx.x * WPB >= cnt) return;   // whole block idle
    int nPart = (cnt + WPB - 1) / WPB;

    int wid = threadIdx.x >> 5;
    int lane = threadIdx.x & 31;
    int j = blockIdx.x * WPB + wid;
    int b = bm / NM;

    if (j < cnt) {
        WarpScratch& S = sp.ws[wid];
        const float2* gp2 = (const float2*)(gt_coor + (size_t)bm * (2*NPT));
        int label = gt_labels[bm];

        int a = g_liveA[bm*MAXL + j];
        float2 ap = ((const float2*)anc)[a];
        float ax = ap.x, ay = ap.y;
        int pairIdx = bm * NA + a;

        // zero 72 bucket counts
        S.scnt[lane] = 0;
        S.scnt[32 + lane] = 0;
        if (lane < 8) S.scnt[64 + lane] = 0;
        __syncwarp();

        // point phase: r2 + angle + bucket (angles/buckets stay in registers)
        float angR[12];
        int   bkR[12];
        #pragma unroll
        for (int i = 0; i < 12; i++) {
            int p = lane + 32*i;
            if (p < NPT) {
                float2 pt = gp2[p];
                float dx = pt.x - ax, dy = pt.y - ay;
                S.r2[p] = dx*dx + dy*dy;
                float ang = atan2f(dy, dx) * 57.29577951308232f;
                if (ang < 0.f) ang += 360.f;
                angR[i] = ang;
                int bk = (int)(ang * 0.2f);
                if (bk > NB2-1) bk = NB2-1;
                bkR[i] = bk;
                atomicAdd(&S.scnt[bk], 1);
            }
        }
        __syncwarp();

        // exclusive scan over 72 counts -> tripled prefix pfx2 + cursors
        {
            int v0 = S.scnt[lane];
            int v1 = S.scnt[32 + lane];
            int v2 = (lane < 8) ? S.scnt[64 + lane] : 0;
            int c0 = v0, c1 = v1, c2 = v2;
            #pragma unroll
            for (int off = 1; off < 32; off <<= 1) {
                int n0 = __shfl_up_sync(FULLM, c0, off);
                int n1 = __shfl_up_sync(FULLM, c1, off);
                if (lane >= off) { c0 += n0; c1 += n1; }
            }
            int tot0 = __shfl_sync(FULLM, c0, 31);
            int tot01 = tot0 + __shfl_sync(FULLM, c1, 31);
            #pragma unroll
            for (int off = 1; off < 8; off <<= 1) {
                int n2 = __shfl_up_sync(FULLM, c2, off);
                if (lane >= off) c2 += n2;
            }
            int e0 = c0 - v0;
            int e1 = tot0 + c1 - v1;
            int e2 = tot01 + c2 - v2;
            S.scur[lane] = e0;
            S.pfx2[lane] = e0; S.pfx2[lane+NB2] = e0+NPT; S.pfx2[lane+2*NB2] = e0+2*NPT;
            int k1i = 32 + lane;
            S.scur[k1i] = e1;
            S.pfx2[k1i] = e1; S.pfx2[k1i+NB2] = e1+NPT; S.pfx2[k1i+2*NB2] = e1+2*NPT;
            if (lane < 8) {
                int k2i = 64 + lane;
                S.scur[k2i] = e2;
                S.pfx2[k2i] = e2; S.pfx2[k2i+NB2] = e2+NPT; S.pfx2[k2i+2*NB2] = e2+2*NPT;
            }
            if (lane == 0) S.pfx2[3*NB2] = 3*NPT;
        }
        __syncwarp();

        // scatter: packed (ang,idx) bucket-contiguous
        #pragma unroll
        for (int i = 0; i < 12; i++) {
            int p = lane + 32*i;
            if (p < NPT) {
                int pos = atomicAdd(&S.scur[bkR[i]], 1);
                S.sAI[pos] = ((unsigned long long)__float_as_uint(angR[i]) << 32) | (unsigned)p;
            }
        }
        __syncwarp();

        // bin phase: one lane per bin, minimal count>=4 ring at 5-deg granularity
        for (int bb = lane; bb < NBINS; bb += 32) {
            int bin = bb;
            int i0 = 2*bin;
            float dmv;
            int c0cnt = S.pfx2[i0+73] - S.pfx2[i0+71];   // buckets 2bin-1,2bin: diff < 5
            if (c0cnt == 0) {
                dmv = 1e-6f;            // nearest candidate diff >= 5 > 3
            } else {
                int L = 0, lo, hi;
                for (;; L++) {
                    lo = S.pfx2[i0+71-L];
                    hi = S.pfx2[i0+73+L];
                    if (hi - lo >= 4) break;
                }
                int W, pos, n1;
                if (2*L + 2 >= NB2) { pos = 0; W = NPT; n1 = NPT; }
                else {
                    W = hi - lo;
                    pos = lo; while (pos >= NPT) pos -= NPT;
                    n1 = NPT - pos; if (n1 > W) n1 = W;
                }

                float th = (float)(bin * 10);
                unsigned long long k0=~0ull,k1=~0ull,k2=~0ull,k3=~0ull;
                for (int c = 0; c < n1; c++) {
                    unsigned long long ai = S.sAI[pos + c];
                    float ang = __uint_as_float((unsigned)(ai >> 32));
                    float df = fabsf(ang - th);
                    if (df > 180.f) df = 360.f - df;
                    ins4(((unsigned long long)__float_as_uint(df) << 32) |
                         (unsigned)(ai & 0xffffffffu), k0, k1, k2, k3);
                }
                for (int c = 0; c < W - n1; c++) {
                    unsigned long long ai = S.sAI[c];
                    float ang = __uint_as_float((unsigned)(ai >> 32));
                    float df = fabsf(ang - th);
                    if (df > 180.f) df = 360.f - df;
                    ins4(((unsigned long long)__float_as_uint(df) << 32) |
                         (unsigned)(ai & 0xffffffffu), k0, k1, k2, k3);
                }
                float mindiff = __uint_as_float((unsigned)(k0 >> 32));
                if (mindiff > 3.0f) {
                    dmv = 1e-6f;
                } else {
                    float mr2 = S.r2[(unsigned)(k0 & 0xffffffffu)];
                    mr2 = fmaxf(mr2, S.r2[(unsigned)(k1 & 0xffffffffu)]);
                    mr2 = fmaxf(mr2, S.r2[(unsigned)(k2 & 0xffffffffu)]);
                    mr2 = fmaxf(mr2, S.r2[(unsigned)(k3 & 0xffffffffu)]);
                    dmv = fmaxf(sqrtf(mr2), 1e-6f);   // sqrt∘max == max∘sqrt
                }
            }
            S.dm[bin] = dmv;
        }
        __syncwarp();

        // coalesced g_dist write
        {
            float* gd = g_dist + (size_t)pairIdx * NBINS;
            gd[lane] = S.dm[lane];
            if (lane < 4) gd[32 + lane] = S.dm[32 + lane];
        }

        // epilogue: iou + centerness + align metric
        {
            float smin = 0.f, smax = 0.f, mn = 1e30f, mx = 0.f;
            const float* pb = pd_bboxes + ((size_t)b*NA + a) * NBINS;
            for (int e = lane; e < NBINS; e += 32) {
                float t = S.dm[e], p = pb[e];
                smin += fmaxf(fminf(t, p), 1e-6f);
                smax += fmaxf(t, p);
                mn = fminf(mn, t);
                mx = fmaxf(mx, t);
            }
            #pragma unroll
            for (int off = 16; off; off >>= 1) {
                smin += __shfl_xor_sync(FULLM, smin, off);
                smax += __shfl_xor_sync(FULLM, smax, off);
                mn = fminf(mn, __shfl_xor_sync(FULLM, mn, off));
                mx = fmaxf(mx, __shfl_xor_sync(FULLM, mx, off));
            }
            if (lane == 0) {
                float iou = smin / smax;
                float score = pd_scores[((size_t)b*NA + a) * NC + label];
                g_overlaps[pairIdx] = iou;
                g_align[pairIdx]    = score * iou * iou * iou;
                g_cent[pairIdx]     = sqrtf(mn / mx);
            }
        }
    }

    // ---- fused top-13: last finishing block of this bm runs the warp topk ----
    __syncthreads();            // also retires all ws usage before s_topk reuse
    if (threadIdx.x == 0) {
        __threadfence();                              // release g_align writes
        int old = atomicAdd(&g_blkdone[bm], 1);
        sLast = (old == nPart - 1) ? 1 : 0;
        if (sLast) g_blkdone[bm] = 0;                 // all arrived; reset for replay
    }
    __syncthreads();
    if (sLast && threadIdx.x < 32) {
        __threadfence();                              // acquire other blocks' writes
        const int* la = g_liveA + bm*MAXL;
        for (int jj = lane; jj < cnt; jj += 32) {
            int a = la[jj];
            float v = g_align[bm*NA + a];
            sp.s_topk[jj] = ((unsigned long long)__float_as_uint(v) << 32) | (unsigned)(NA - a);
        }
        __syncwarp();
        int m = bm % NM;
        int kmax = cnt < 13 ? cnt : 13;
        for (int k = 0; k < kmax; k++) {
            unsigned long long best = 0;
            for (int jj = lane; jj < cnt; jj += 32) best = ullmax2(best, sp.s_topk[jj]);
            #pragma unroll
            for (int off = 16; off; off >>= 1)
                best = ullmax2(best, __shfl_xor_sync(FULLM, best, off));
            if (best == 0) break;   // padding picks carry mask_pos=0 in reference
            for (int jj = lane; jj < cnt; jj += 32) if (sp.s_topk[jj] == best) sp.s_topk[jj] = 0;
            if (lane == 0) {
                int a = NA - (int)(best & 0xffffffffu);
                atomicOr(&g_topkbits[b*NA + a], 1u << m);
            }
            __syncwarp();
        }
    }
}

// ---------------------------------------------------------------------------
// K3: fused per-anchor resolution + outputs + grid barrier + target_scores
// ---------------------------------------------------------------------------
__global__ __launch_bounds__(256) void k_assign(
    const int*   __restrict__ gt_labels,
    const float* __restrict__ gt_bboxes,
    float* __restrict__ out)
{
    int t = blockIdx.x * blockDim.x + threadIdx.x;
    bool valid = t < BSNA;
    unsigned fin = 0;
    int b = 0, a = 0;

    if (valid) {
        b = t / NA; a = t % NA;
        unsigned tb  = g_topkbits[t];
        unsigned inb = g_inbits[t];
        g_topkbits[t] = 0u;               // reset for next replay
        g_inbits[t]   = 0u;               // reset (compact now ORs sparsely)
        fin = tb;
        if (__popc(tb) > 1) {
            float best = -1.f; int bi = 0;
            #pragma unroll
            for (int m = 0; m < NM; m++) {
                float o = ((inb >> m) & 1u) ? g_overlaps[(b*NM+m)*NA + a] : 0.f;
                if (o > best) { best = o; bi = m; }   // first max kept
            }
            fin = 1u << bi;
        }

        int tgt = fin ? (__ffs(fin) - 1) : 0;
        out[FG_OFF + t]  = fin ? 1.f : 0.f;
        out[TGI_OFF + t] = (float)tgt;
        int lbl = gt_labels[b*NM + tgt]; if (lbl < 0) lbl = 0;
        out[TL_OFF + t] = (float)lbl;
        const float4* gb4 = (const float4*)(gt_bboxes);
        ((float4*)(out + TB_OFF))[t] = gb4[b*NM + tgt];

        if (fin) {
            int idx = (b*NM + tgt)*NA + a;
            out[MPB_OFF + idx]  = 1.f;
            out[CENT_OFF + idx] = g_cent[idx];
            atomicMax(&g_posA[b*NM + tgt], __float_as_uint(g_align[idx]));
            atomicMax(&g_posO[b*NM + tgt], __float_as_uint(g_overlaps[idx]));
            const float4* src = (const float4*)(g_dist + (size_t)idx * NBINS);
            float4* dst = (float4*)(out + GTDIST_OFF + (size_t)idx * NBINS);
            #pragma unroll
            for (int e = 0; e < NBINS/4; e++) dst[e] = src[e];
        }
    }
    if (t < NBM) g_cnt[t] = 0;            // reset for next replay (k_pairs done)

    // ---- software grid barrier (two counters; all ABLK blocks co-resident) ----
    if (threadIdx.x == 0) {
        __threadfence();
        atomicAdd(&g_bar1, 1u);
        while (*((volatile unsigned*)&g_bar1) < ABLK) { }
        __threadfence();
        unsigned o2 = atomicAdd(&g_bar2, 1u);
        if (o2 == ABLK - 1) {             // everyone passed the spin
            atomicExch(&g_bar1, 0u);
            atomicExch(&g_bar2, 0u);
        }
    }
    __syncthreads();

    // ---- phase 2: target_scores for positives ----
    if (valid && fin) {
        int m = __ffs(fin) - 1;
        int bm = b*NM + m;
        float A = __uint_as_float(g_posA[bm]);
        float O = __uint_as_float(g_posO[bm]);
        float norm = g_align[bm*NA + a] * O / (A + 1e-9f);
        int lbl = gt_labels[bm]; if (lbl < 0) lbl = 0;
        out[TS_OFF + (size_t)t * NC + lbl] = norm;
    }
}

// ---------------------------------------------------------------------------
// Stream order: compact -> pairs -> memset -> assign.
// (memset only has to precede assign; placing it third makes launch index 5
//  land on iter-1's k_pairs so ncu -s 5 -c 1 finally profiles the hot kernel.)
// ---------------------------------------------------------------------------
extern "C" void kernel_launch(void* const* d_in, const int* in_sizes, int n_in,
                              void* d_out, int out_size) {
    const float* pd_scores = (const float*)d_in[0];
    const float* pd_bboxes = (const float*)d_in[1];
    const float* anc       = (const float*)d_in[2];
    const int*   gt_labels = (const int*)  d_in[3];
    const float* gt_bboxes = (const float*)d_in[4];
    const float* mask_gt   = (const float*)d_in[5];
    const float* gt_coor   = (const float*)d_in[6];
    float* out = (float*)d_out;

    k_compact<<<(NBM*NAP + 255)/256, 256>>>(anc, gt_bboxes, mask_gt);
    dim3 g1((MAXL + WPB - 1)/WPB, NBM);
    k_pairs<<<g1, 32*WPB>>>(pd_scores, pd_bboxes, anc, gt_labels, gt_coor);
    cudaMemsetAsync(out, 0, (size_t)OUT_TOTAL * sizeof(float));
    k_assign<<<ABLK, 256>>>(gt_labels, gt_bboxes, out);
}